// round 2
// baseline (speedup 1.0000x reference)
#include <cuda_runtime.h>

// Problem constants
#define BS_TOT 32768   // B*S = 8*4096
#define DK     1024    // D (reduction dim)
#define OO     1024    // O (output features)
#define RR     16      // LoRA rank
#define TT     4       // tasks
#define NJ     80      // (1+T)*R concatenated LoRA-A rows

// Scratch for XA = x @ Acat^T  ([BS_TOT, 80] fp32, ~10.5 MB, static device alloc)
__device__ float g_xa[(size_t)BS_TOT * NJ];

__device__ __forceinline__ float f2tf(float x) {
    unsigned int u;
    asm("cvt.rna.tf32.f32 %0, %1;" : "=r"(u) : "f"(x));
    return __uint_as_float(u);
}

__device__ __forceinline__ void mma_tf32(float c[4], const unsigned int a[4],
                                         const unsigned int b[2]) {
    asm volatile(
        "mma.sync.aligned.m16n8k8.row.col.f32.tf32.tf32.f32 "
        "{%0,%1,%2,%3}, {%4,%5,%6,%7}, {%8,%9}, {%0,%1,%2,%3};"
        : "+f"(c[0]), "+f"(c[1]), "+f"(c[2]), "+f"(c[3])
        : "r"(a[0]), "r"(a[1]), "r"(a[2]), "r"(a[3]), "r"(b[0]), "r"(b[1]));
}

// ---------------------------------------------------------------------------
// Kernel 1: XA[m, j] = sum_d x[m,d] * Acat[j,d],  Acat = [A_sh(16); A_tasks(64)]
// CTA: 128 rows x 80 cols, BK=32. 8 warps as 4(m) x 2(n); warp tile 32x40.
// ---------------------------------------------------------------------------
__global__ __launch_bounds__(256, 1)
void xa_kernel(const float* __restrict__ x, const float* __restrict__ A_sh,
               const float* __restrict__ A_tasks) {
    __shared__ float xs[128][36];
    __shared__ float as[NJ][36];
    const int tid  = threadIdx.x;
    const int lane = tid & 31;
    const int wid  = tid >> 5;
    const int wm   = (wid >> 1) * 32;   // warp m offset (0..96)
    const int wn   = (wid & 1) * 40;    // warp n offset (0 or 40)
    const int g    = lane >> 2;         // groupID
    const int t    = lane & 3;          // threadID_in_group
    const int blockM = blockIdx.x * 128;

    float c[2][5][4];
#pragma unroll
    for (int i = 0; i < 2; i++)
#pragma unroll
        for (int j = 0; j < 5; j++)
#pragma unroll
            for (int k = 0; k < 4; k++) c[i][j][k] = 0.f;

    float4 xr[4];
    float4 ar[3];

    // ---- prefetch tile k0 = 0 ----
    {
        const int k0 = 0;
#pragma unroll
        for (int i = 0; i < 4; i++) {
            int f = tid + i * 256, row = f >> 3, kq = f & 7;
            xr[i] = *(const float4*)(x + (size_t)(blockM + row) * DK + k0 + kq * 4);
        }
#pragma unroll
        for (int i = 0; i < 3; i++) {
            int f = tid + i * 256;
            if (f < NJ * 8) {
                int row = f >> 3, kq = f & 7;
                const float* src = (row < RR) ? (A_sh + (size_t)row * DK)
                                              : (A_tasks + (size_t)(row - RR) * DK);
                ar[i] = *(const float4*)(src + k0 + kq * 4);
            }
        }
    }
    // store tile 0
#pragma unroll
    for (int i = 0; i < 4; i++) {
        int f = tid + i * 256, row = f >> 3, kq = f & 7;
        xs[row][kq * 4 + 0] = f2tf(xr[i].x); xs[row][kq * 4 + 1] = f2tf(xr[i].y);
        xs[row][kq * 4 + 2] = f2tf(xr[i].z); xs[row][kq * 4 + 3] = f2tf(xr[i].w);
    }
#pragma unroll
    for (int i = 0; i < 3; i++) {
        int f = tid + i * 256;
        if (f < NJ * 8) {
            int row = f >> 3, kq = f & 7;
            as[row][kq * 4 + 0] = f2tf(ar[i].x); as[row][kq * 4 + 1] = f2tf(ar[i].y);
            as[row][kq * 4 + 2] = f2tf(ar[i].z); as[row][kq * 4 + 3] = f2tf(ar[i].w);
        }
    }
    __syncthreads();

    for (int kt = 0; kt < DK / 32; ++kt) {
        // issue next tile's global loads early
        if (kt + 1 < DK / 32) {
            const int k0 = (kt + 1) * 32;
#pragma unroll
            for (int i = 0; i < 4; i++) {
                int f = tid + i * 256, row = f >> 3, kq = f & 7;
                xr[i] = *(const float4*)(x + (size_t)(blockM + row) * DK + k0 + kq * 4);
            }
#pragma unroll
            for (int i = 0; i < 3; i++) {
                int f = tid + i * 256;
                if (f < NJ * 8) {
                    int row = f >> 3, kq = f & 7;
                    const float* src = (row < RR) ? (A_sh + (size_t)row * DK)
                                                  : (A_tasks + (size_t)(row - RR) * DK);
                    ar[i] = *(const float4*)(src + k0 + kq * 4);
                }
            }
        }
        // compute on current smem tile
#pragma unroll
        for (int ks = 0; ks < 4; ++ks) {
            const int k = ks * 8;
            unsigned int a[2][4], b[5][2];
#pragma unroll
            for (int mt = 0; mt < 2; mt++) {
                int m = wm + mt * 16;
                a[mt][0] = __float_as_uint(xs[m + g][k + t]);
                a[mt][1] = __float_as_uint(xs[m + g + 8][k + t]);
                a[mt][2] = __float_as_uint(xs[m + g][k + t + 4]);
                a[mt][3] = __float_as_uint(xs[m + g + 8][k + t + 4]);
            }
#pragma unroll
            for (int nt = 0; nt < 5; nt++) {
                int n = wn + nt * 8;
                b[nt][0] = __float_as_uint(as[n + g][k + t]);
                b[nt][1] = __float_as_uint(as[n + g][k + t + 4]);
            }
#pragma unroll
            for (int mt = 0; mt < 2; mt++)
#pragma unroll
                for (int nt = 0; nt < 5; nt++) mma_tf32(c[mt][nt], a[mt], b[nt]);
        }
        __syncthreads();
        if (kt + 1 < DK / 32) {
#pragma unroll
            for (int i = 0; i < 4; i++) {
                int f = tid + i * 256, row = f >> 3, kq = f & 7;
                xs[row][kq * 4 + 0] = f2tf(xr[i].x); xs[row][kq * 4 + 1] = f2tf(xr[i].y);
                xs[row][kq * 4 + 2] = f2tf(xr[i].z); xs[row][kq * 4 + 3] = f2tf(xr[i].w);
            }
#pragma unroll
            for (int i = 0; i < 3; i++) {
                int f = tid + i * 256;
                if (f < NJ * 8) {
                    int row = f >> 3, kq = f & 7;
                    as[row][kq * 4 + 0] = f2tf(ar[i].x); as[row][kq * 4 + 1] = f2tf(ar[i].y);
                    as[row][kq * 4 + 2] = f2tf(ar[i].z); as[row][kq * 4 + 3] = f2tf(ar[i].w);
                }
            }
            __syncthreads();
        }
    }

    // store XA (fp32)
#pragma unroll
    for (int mt = 0; mt < 2; mt++)
#pragma unroll
        for (int nt = 0; nt < 5; nt++) {
            int m = blockM + wm + mt * 16 + g;
            int n = wn + nt * 8 + 2 * t;
            *(float2*)(g_xa + (size_t)m * NJ + n) =
                make_float2(c[mt][nt][0], c[mt][nt][1]);
            *(float2*)(g_xa + (size_t)(m + 8) * NJ + n) =
                make_float2(c[mt][nt][2], c[mt][nt][3]);
        }
}

// ---------------------------------------------------------------------------
// Kernel 2: P = x@W^T (tf32 mma) ; epilogue adds bias + per-slice rank-16
// correction via mma over XA (global) x Bcat (global), writes 5 output slices.
// CTA 128x128, BK=32, 8 warps as 2(m) x 4(n); warp tile 64x32.
// ---------------------------------------------------------------------------
__global__ __launch_bounds__(256, 1)
void main_kernel(const float* __restrict__ x, const float* __restrict__ W,
                 const float* __restrict__ bias, const float* __restrict__ B_sh,
                 const float* __restrict__ B_tasks, const float* __restrict__ tsc,
                 float* __restrict__ out) {
    __shared__ float As[128][36];  // x tile   [m][k]
    __shared__ float Ws[128][36];  // W tile   [o][k]
    const int tid  = threadIdx.x;
    const int lane = tid & 31;
    const int wid  = tid >> 5;
    const int wm   = (wid >> 2) * 64;  // warp m offset (0 or 64)
    const int wn   = (wid & 3) * 32;   // warp n offset (0..96)
    const int g    = lane >> 2;
    const int t    = lane & 3;
    const int blockN = blockIdx.x * 128;
    const int blockM = blockIdx.y * 128;

    float c[4][4][4];
#pragma unroll
    for (int i = 0; i < 4; i++)
#pragma unroll
        for (int j = 0; j < 4; j++)
#pragma unroll
            for (int k = 0; k < 4; k++) c[i][j][k] = 0.f;

    float4 xr[4], wr[4];

    // prefetch tile 0
    {
        const int k0 = 0;
#pragma unroll
        for (int i = 0; i < 4; i++) {
            int f = tid + i * 256, row = f >> 3, kq = f & 7;
            xr[i] = *(const float4*)(x + (size_t)(blockM + row) * DK + k0 + kq * 4);
            wr[i] = *(const float4*)(W + (size_t)(blockN + row) * DK + k0 + kq * 4);
        }
    }
#pragma unroll
    for (int i = 0; i < 4; i++) {
        int f = tid + i * 256, row = f >> 3, kq = f & 7;
        As[row][kq * 4 + 0] = f2tf(xr[i].x); As[row][kq * 4 + 1] = f2tf(xr[i].y);
        As[row][kq * 4 + 2] = f2tf(xr[i].z); As[row][kq * 4 + 3] = f2tf(xr[i].w);
        Ws[row][kq * 4 + 0] = f2tf(wr[i].x); Ws[row][kq * 4 + 1] = f2tf(wr[i].y);
        Ws[row][kq * 4 + 2] = f2tf(wr[i].z); Ws[row][kq * 4 + 3] = f2tf(wr[i].w);
    }
    __syncthreads();

    for (int kt = 0; kt < DK / 32; ++kt) {
        if (kt + 1 < DK / 32) {
            const int k0 = (kt + 1) * 32;
#pragma unroll
            for (int i = 0; i < 4; i++) {
                int f = tid + i * 256, row = f >> 3, kq = f & 7;
                xr[i] = *(const float4*)(x + (size_t)(blockM + row) * DK + k0 + kq * 4);
                wr[i] = *(const float4*)(W + (size_t)(blockN + row) * DK + k0 + kq * 4);
            }
        }
#pragma unroll
        for (int ks = 0; ks < 4; ++ks) {
            const int k = ks * 8;
            unsigned int a[4][4], b[4][2];
#pragma unroll
            for (int mt = 0; mt < 4; mt++) {
                int m = wm + mt * 16;
                a[mt][0] = __float_as_uint(As[m + g][k + t]);
                a[mt][1] = __float_as_uint(As[m + g + 8][k + t]);
                a[mt][2] = __float_as_uint(As[m + g][k + t + 4]);
                a[mt][3] = __float_as_uint(As[m + g + 8][k + t + 4]);
            }
#pragma unroll
            for (int nt = 0; nt < 4; nt++) {
                int n = wn + nt * 8;
                b[nt][0] = __float_as_uint(Ws[n + g][k + t]);
                b[nt][1] = __float_as_uint(Ws[n + g][k + t + 4]);
            }
#pragma unroll
            for (int mt = 0; mt < 4; mt++)
#pragma unroll
                for (int nt = 0; nt < 4; nt++) mma_tf32(c[mt][nt], a[mt], b[nt]);
        }
        __syncthreads();
        if (kt + 1 < DK / 32) {
#pragma unroll
            for (int i = 0; i < 4; i++) {
                int f = tid + i * 256, row = f >> 3, kq = f & 7;
                As[row][kq * 4 + 0] = f2tf(xr[i].x); As[row][kq * 4 + 1] = f2tf(xr[i].y);
                As[row][kq * 4 + 2] = f2tf(xr[i].z); As[row][kq * 4 + 3] = f2tf(xr[i].w);
                Ws[row][kq * 4 + 0] = f2tf(wr[i].x); Ws[row][kq * 4 + 1] = f2tf(wr[i].y);
                Ws[row][kq * 4 + 2] = f2tf(wr[i].z); Ws[row][kq * 4 + 3] = f2tf(wr[i].w);
            }
            __syncthreads();
        }
    }

    // ---- epilogue ----
    // bias add (bias is part of pretrained P, present in all 5 slices)
#pragma unroll
    for (int nt = 0; nt < 4; nt++) {
        float2 bb = *(const float2*)(bias + blockN + wn + nt * 8 + 2 * t);
#pragma unroll
        for (int mt = 0; mt < 4; mt++) {
            c[mt][nt][0] += bb.x; c[mt][nt][1] += bb.y;
            c[mt][nt][2] += bb.x; c[mt][nt][3] += bb.y;
        }
    }
    float ts[TT];
#pragma unroll
    for (int i = 0; i < TT; i++) ts[i] = __ldg(tsc + i);

    for (int s = 0; s < 1 + TT; s++) {
        const float scale = (s == 0) ? 1.f : ts[s - 1];
        const float* Bp = (s == 0) ? B_sh : (B_tasks + (size_t)(s - 1) * OO * RR);
        float acc2[4][4][4];
#pragma unroll
        for (int i = 0; i < 4; i++)
#pragma unroll
            for (int j = 0; j < 4; j++)
#pragma unroll
                for (int k = 0; k < 4; k++) acc2[i][j][k] = 0.f;

#pragma unroll
        for (int kst = 0; kst < 2; kst++) {
            const int j0 = s * RR + kst * 8;
            unsigned int a[4][4], b[4][2];
#pragma unroll
            for (int mt = 0; mt < 4; mt++) {
                int m = blockM + wm + mt * 16 + g;
                const float* xa0 = g_xa + (size_t)m * NJ + j0 + t;
                a[mt][0] = __float_as_uint(xa0[0]);
                a[mt][1] = __float_as_uint(xa0[8 * NJ]);
                a[mt][2] = __float_as_uint(xa0[4]);
                a[mt][3] = __float_as_uint(xa0[8 * NJ + 4]);
            }
            const int r0 = kst * 8 + t;
#pragma unroll
            for (int nt = 0; nt < 4; nt++) {
                int o = blockN + wn + nt * 8 + g;
                b[nt][0] = __float_as_uint(Bp[(size_t)o * RR + r0]);
                b[nt][1] = __float_as_uint(Bp[(size_t)o * RR + r0 + 4]);
            }
#pragma unroll
            for (int mt = 0; mt < 4; mt++)
#pragma unroll
                for (int nt = 0; nt < 4; nt++) mma_tf32(acc2[mt][nt], a[mt], b[nt]);
        }

        // write this slice
#pragma unroll
        for (int mt = 0; mt < 4; mt++)
#pragma unroll
            for (int nt = 0; nt < 4; nt++) {
                int m = blockM + wm + mt * 16 + g;
                int o = blockN + wn + nt * 8 + 2 * t;
                size_t base = ((size_t)s * BS_TOT + m) * OO + o;
                float2 v0 = make_float2(c[mt][nt][0] + scale * acc2[mt][nt][0],
                                        c[mt][nt][1] + scale * acc2[mt][nt][1]);
                float2 v1 = make_float2(c[mt][nt][2] + scale * acc2[mt][nt][2],
                                        c[mt][nt][3] + scale * acc2[mt][nt][3]);
                *(float2*)(out + base) = v0;
                *(float2*)(out + base + (size_t)8 * OO) = v1;
            }
    }
}

extern "C" void kernel_launch(void* const* d_in, const int* in_sizes, int n_in,
                              void* d_out, int out_size) {
    (void)in_sizes; (void)n_in; (void)out_size;
    const float* x        = (const float*)d_in[0];
    const float* W        = (const float*)d_in[1];
    const float* b        = (const float*)d_in[2];
    const float* A_sh     = (const float*)d_in[3];
    const float* B_sh     = (const float*)d_in[4];
    const float* A_tasks  = (const float*)d_in[5];
    const float* B_tasks  = (const float*)d_in[6];
    const float* tsc      = (const float*)d_in[7];
    float* out            = (float*)d_out;

    xa_kernel<<<BS_TOT / 128, 256>>>(x, A_sh, A_tasks);
    dim3 grid(OO / 128, BS_TOT / 128);
    main_kernel<<<grid, 256>>>(x, W, b, B_sh, B_tasks, tsc, out);
}

// round 5
// speedup vs baseline: 1.0028x; 1.0028x over previous
#include <cuda_runtime.h>

// Problem constants
#define BS_TOT 32768   // B*S = 8*4096
#define DK     1024    // D (reduction dim)
#define OO     1024    // O (output features)
#define RR     16      // LoRA rank
#define TT     4       // tasks
#define NJ     80      // (1+T)*R concatenated LoRA-A rows

// Scratch for XA = x @ Acat^T  ([BS_TOT, 80] fp32, ~10.5 MB, static device alloc)
__device__ float g_xa[(size_t)BS_TOT * NJ];

__device__ __forceinline__ float f2tf(float x) {
    unsigned int u;
    asm("cvt.rna.tf32.f32 %0, %1;" : "=r"(u) : "f"(x));
    return __uint_as_float(u);
}

__device__ __forceinline__ void mma_tf32(float c[4], const unsigned int a[4],
                                         const unsigned int b[2]) {
    asm volatile(
        "mma.sync.aligned.m16n8k8.row.col.f32.tf32.tf32.f32 "
        "{%0,%1,%2,%3}, {%4,%5,%6,%7}, {%8,%9}, {%0,%1,%2,%3};"
        : "+f"(c[0]), "+f"(c[1]), "+f"(c[2]), "+f"(c[3])
        : "r"(a[0]), "r"(a[1]), "r"(a[2]), "r"(a[3]), "r"(b[0]), "r"(b[1]));
}

// ---------------------------------------------------------------------------
// Kernel 1: XA[m, j] = sum_d x[m,d] * Acat[j,d],  Acat = [A_sh(16); A_tasks(64)]
// CTA: 128 rows x 80 cols, BK=32. 8 warps as 4(m) x 2(n); warp tile 32x40.
// ---------------------------------------------------------------------------
__global__ __launch_bounds__(256, 1)
void xa_kernel(const float* __restrict__ x, const float* __restrict__ A_sh,
               const float* __restrict__ A_tasks) {
    __shared__ float xs[128][36];
    __shared__ float as[NJ][36];
    const int tid  = threadIdx.x;
    const int lane = tid & 31;
    const int wid  = tid >> 5;
    const int wm   = (wid >> 1) * 32;   // warp m offset (0..96)
    const int wn   = (wid & 1) * 40;    // warp n offset (0 or 40)
    const int g    = lane >> 2;         // groupID
    const int t    = lane & 3;          // threadID_in_group
    const int blockM = blockIdx.x * 128;

    float c[2][5][4];
#pragma unroll
    for (int i = 0; i < 2; i++)
#pragma unroll
        for (int j = 0; j < 5; j++)
#pragma unroll
            for (int k = 0; k < 4; k++) c[i][j][k] = 0.f;

    float4 xr[4];
    float4 ar[3];

    // ---- prefetch tile k0 = 0 ----
    {
        const int k0 = 0;
#pragma unroll
        for (int i = 0; i < 4; i++) {
            int f = tid + i * 256, row = f >> 3, kq = f & 7;
            xr[i] = *(const float4*)(x + (size_t)(blockM + row) * DK + k0 + kq * 4);
        }
#pragma unroll
        for (int i = 0; i < 3; i++) {
            int f = tid + i * 256;
            if (f < NJ * 8) {
                int row = f >> 3, kq = f & 7;
                const float* src = (row < RR) ? (A_sh + (size_t)row * DK)
                                              : (A_tasks + (size_t)(row - RR) * DK);
                ar[i] = *(const float4*)(src + k0 + kq * 4);
            }
        }
    }
    // store tile 0
#pragma unroll
    for (int i = 0; i < 4; i++) {
        int f = tid + i * 256, row = f >> 3, kq = f & 7;
        xs[row][kq * 4 + 0] = f2tf(xr[i].x); xs[row][kq * 4 + 1] = f2tf(xr[i].y);
        xs[row][kq * 4 + 2] = f2tf(xr[i].z); xs[row][kq * 4 + 3] = f2tf(xr[i].w);
    }
#pragma unroll
    for (int i = 0; i < 3; i++) {
        int f = tid + i * 256;
        if (f < NJ * 8) {
            int row = f >> 3, kq = f & 7;
            as[row][kq * 4 + 0] = f2tf(ar[i].x); as[row][kq * 4 + 1] = f2tf(ar[i].y);
            as[row][kq * 4 + 2] = f2tf(ar[i].z); as[row][kq * 4 + 3] = f2tf(ar[i].w);
        }
    }
    __syncthreads();

    for (int kt = 0; kt < DK / 32; ++kt) {
        // issue next tile's global loads early
        if (kt + 1 < DK / 32) {
            const int k0 = (kt + 1) * 32;
#pragma unroll
            for (int i = 0; i < 4; i++) {
                int f = tid + i * 256, row = f >> 3, kq = f & 7;
                xr[i] = *(const float4*)(x + (size_t)(blockM + row) * DK + k0 + kq * 4);
            }
#pragma unroll
            for (int i = 0; i < 3; i++) {
                int f = tid + i * 256;
                if (f < NJ * 8) {
                    int row = f >> 3, kq = f & 7;
                    const float* src = (row < RR) ? (A_sh + (size_t)row * DK)
                                                  : (A_tasks + (size_t)(row - RR) * DK);
                    ar[i] = *(const float4*)(src + k0 + kq * 4);
                }
            }
        }
        // compute on current smem tile
#pragma unroll
        for (int ks = 0; ks < 4; ++ks) {
            const int k = ks * 8;
            unsigned int a[2][4], b[5][2];
#pragma unroll
            for (int mt = 0; mt < 2; mt++) {
                int m = wm + mt * 16;
                a[mt][0] = __float_as_uint(xs[m + g][k + t]);
                a[mt][1] = __float_as_uint(xs[m + g + 8][k + t]);
                a[mt][2] = __float_as_uint(xs[m + g][k + t + 4]);
                a[mt][3] = __float_as_uint(xs[m + g + 8][k + t + 4]);
            }
#pragma unroll
            for (int nt = 0; nt < 5; nt++) {
                int n = wn + nt * 8;
                b[nt][0] = __float_as_uint(as[n + g][k + t]);
                b[nt][1] = __float_as_uint(as[n + g][k + t + 4]);
            }
#pragma unroll
            for (int mt = 0; mt < 2; mt++)
#pragma unroll
                for (int nt = 0; nt < 5; nt++) mma_tf32(c[mt][nt], a[mt], b[nt]);
        }
        __syncthreads();
        if (kt + 1 < DK / 32) {
#pragma unroll
            for (int i = 0; i < 4; i++) {
                int f = tid + i * 256, row = f >> 3, kq = f & 7;
                xs[row][kq * 4 + 0] = f2tf(xr[i].x); xs[row][kq * 4 + 1] = f2tf(xr[i].y);
                xs[row][kq * 4 + 2] = f2tf(xr[i].z); xs[row][kq * 4 + 3] = f2tf(xr[i].w);
            }
#pragma unroll
            for (int i = 0; i < 3; i++) {
                int f = tid + i * 256;
                if (f < NJ * 8) {
                    int row = f >> 3, kq = f & 7;
                    as[row][kq * 4 + 0] = f2tf(ar[i].x); as[row][kq * 4 + 1] = f2tf(ar[i].y);
                    as[row][kq * 4 + 2] = f2tf(ar[i].z); as[row][kq * 4 + 3] = f2tf(ar[i].w);
                }
            }
            __syncthreads();
        }
    }

    // store XA (fp32)
#pragma unroll
    for (int mt = 0; mt < 2; mt++)
#pragma unroll
        for (int nt = 0; nt < 5; nt++) {
            int m = blockM + wm + mt * 16 + g;
            int n = wn + nt * 8 + 2 * t;
            *(float2*)(g_xa + (size_t)m * NJ + n) =
                make_float2(c[mt][nt][0], c[mt][nt][1]);
            *(float2*)(g_xa + (size_t)(m + 8) * NJ + n) =
                make_float2(c[mt][nt][2], c[mt][nt][3]);
        }
}

// ---------------------------------------------------------------------------
// Kernel 2: P = x@W^T (tf32 mma) ; epilogue adds bias + per-slice rank-16
// correction via mma over XA (global) x Bcat (global), writes 5 output slices.
// CTA 128x128, BK=32, 8 warps as 2(m) x 4(n); warp tile 64x32.
// ---------------------------------------------------------------------------
__global__ __launch_bounds__(256, 1)
void main_kernel(const float* __restrict__ x, const float* __restrict__ W,
                 const float* __restrict__ bias, const float* __restrict__ B_sh,
                 const float* __restrict__ B_tasks, const float* __restrict__ tsc,
                 float* __restrict__ out) {
    __shared__ float As[128][36];  // x tile   [m][k]
    __shared__ float Ws[128][36];  // W tile   [o][k]
    const int tid  = threadIdx.x;
    const int lane = tid & 31;
    const int wid  = tid >> 5;
    const int wm   = (wid >> 2) * 64;  // warp m offset (0 or 64)
    const int wn   = (wid & 3) * 32;   // warp n offset (0..96)
    const int g    = lane >> 2;
    const int t    = lane & 3;
    const int blockN = blockIdx.x * 128;
    const int blockM = blockIdx.y * 128;

    float c[4][4][4];
#pragma unroll
    for (int i = 0; i < 4; i++)
#pragma unroll
        for (int j = 0; j < 4; j++)
#pragma unroll
            for (int k = 0; k < 4; k++) c[i][j][k] = 0.f;

    float4 xr[4], wr[4];

    // prefetch tile 0
    {
        const int k0 = 0;
#pragma unroll
        for (int i = 0; i < 4; i++) {
            int f = tid + i * 256, row = f >> 3, kq = f & 7;
            xr[i] = *(const float4*)(x + (size_t)(blockM + row) * DK + k0 + kq * 4);
            wr[i] = *(const float4*)(W + (size_t)(blockN + row) * DK + k0 + kq * 4);
        }
    }
#pragma unroll
    for (int i = 0; i < 4; i++) {
        int f = tid + i * 256, row = f >> 3, kq = f & 7;
        As[row][kq * 4 + 0] = f2tf(xr[i].x); As[row][kq * 4 + 1] = f2tf(xr[i].y);
        As[row][kq * 4 + 2] = f2tf(xr[i].z); As[row][kq * 4 + 3] = f2tf(xr[i].w);
        Ws[row][kq * 4 + 0] = f2tf(wr[i].x); Ws[row][kq * 4 + 1] = f2tf(wr[i].y);
        Ws[row][kq * 4 + 2] = f2tf(wr[i].z); Ws[row][kq * 4 + 3] = f2tf(wr[i].w);
    }
    __syncthreads();

    for (int kt = 0; kt < DK / 32; ++kt) {
        if (kt + 1 < DK / 32) {
            const int k0 = (kt + 1) * 32;
#pragma unroll
            for (int i = 0; i < 4; i++) {
                int f = tid + i * 256, row = f >> 3, kq = f & 7;
                xr[i] = *(const float4*)(x + (size_t)(blockM + row) * DK + k0 + kq * 4);
                wr[i] = *(const float4*)(W + (size_t)(blockN + row) * DK + k0 + kq * 4);
            }
        }
#pragma unroll
        for (int ks = 0; ks < 4; ++ks) {
            const int k = ks * 8;
            unsigned int a[4][4], b[4][2];
#pragma unroll
            for (int mt = 0; mt < 4; mt++) {
                int m = wm + mt * 16;
                a[mt][0] = __float_as_uint(As[m + g][k + t]);
                a[mt][1] = __float_as_uint(As[m + g + 8][k + t]);
                a[mt][2] = __float_as_uint(As[m + g][k + t + 4]);
                a[mt][3] = __float_as_uint(As[m + g + 8][k + t + 4]);
            }
#pragma unroll
            for (int nt = 0; nt < 4; nt++) {
                int n = wn + nt * 8;
                b[nt][0] = __float_as_uint(Ws[n + g][k + t]);
                b[nt][1] = __float_as_uint(Ws[n + g][k + t + 4]);
            }
#pragma unroll
            for (int mt = 0; mt < 4; mt++)
#pragma unroll
                for (int nt = 0; nt < 4; nt++) mma_tf32(c[mt][nt], a[mt], b[nt]);
        }
        __syncthreads();
        if (kt + 1 < DK / 32) {
#pragma unroll
            for (int i = 0; i < 4; i++) {
                int f = tid + i * 256, row = f >> 3, kq = f & 7;
                As[row][kq * 4 + 0] = f2tf(xr[i].x); As[row][kq * 4 + 1] = f2tf(xr[i].y);
                As[row][kq * 4 + 2] = f2tf(xr[i].z); As[row][kq * 4 + 3] = f2tf(xr[i].w);
                Ws[row][kq * 4 + 0] = f2tf(wr[i].x); Ws[row][kq * 4 + 1] = f2tf(wr[i].y);
                Ws[row][kq * 4 + 2] = f2tf(wr[i].z); Ws[row][kq * 4 + 3] = f2tf(wr[i].w);
            }
            __syncthreads();
        }
    }

    // ---- epilogue ----
    // bias add (bias is part of pretrained P, present in all 5 slices)
#pragma unroll
    for (int nt = 0; nt < 4; nt++) {
        float2 bb = *(const float2*)(bias + blockN + wn + nt * 8 + 2 * t);
#pragma unroll
        for (int mt = 0; mt < 4; mt++) {
            c[mt][nt][0] += bb.x; c[mt][nt][1] += bb.y;
            c[mt][nt][2] += bb.x; c[mt][nt][3] += bb.y;
        }
    }
    float ts[TT];
#pragma unroll
    for (int i = 0; i < TT; i++) ts[i] = __ldg(tsc + i);

    for (int s = 0; s < 1 + TT; s++) {
        const float scale = (s == 0) ? 1.f : ts[s - 1];
        const float* Bp = (s == 0) ? B_sh : (B_tasks + (size_t)(s - 1) * OO * RR);
        float acc2[4][4][4];
#pragma unroll
        for (int i = 0; i < 4; i++)
#pragma unroll
            for (int j = 0; j < 4; j++)
#pragma unroll
                for (int k = 0; k < 4; k++) acc2[i][j][k] = 0.f;

#pragma unroll
        for (int kst = 0; kst < 2; kst++) {
            const int j0 = s * RR + kst * 8;
            unsigned int a[4][4], b[4][2];
#pragma unroll
            for (int mt = 0; mt < 4; mt++) {
                int m = blockM + wm + mt * 16 + g;
                const float* xa0 = g_xa + (size_t)m * NJ + j0 + t;
                a[mt][0] = __float_as_uint(xa0[0]);
                a[mt][1] = __float_as_uint(xa0[8 * NJ]);
                a[mt][2] = __float_as_uint(xa0[4]);
                a[mt][3] = __float_as_uint(xa0[8 * NJ + 4]);
            }
            const int r0 = kst * 8 + t;
#pragma unroll
            for (int nt = 0; nt < 4; nt++) {
                int o = blockN + wn + nt * 8 + g;
                b[nt][0] = __float_as_uint(Bp[(size_t)o * RR + r0]);
                b[nt][1] = __float_as_uint(Bp[(size_t)o * RR + r0 + 4]);
            }
#pragma unroll
            for (int mt = 0; mt < 4; mt++)
#pragma unroll
                for (int nt = 0; nt < 4; nt++) mma_tf32(acc2[mt][nt], a[mt], b[nt]);
        }

        // write this slice
#pragma unroll
        for (int mt = 0; mt < 4; mt++)
#pragma unroll
            for (int nt = 0; nt < 4; nt++) {
                int m = blockM + wm + mt * 16 + g;
                int o = blockN + wn + nt * 8 + 2 * t;
                size_t base = ((size_t)s * BS_TOT + m) * OO + o;
                float2 v0 = make_float2(c[mt][nt][0] + scale * acc2[mt][nt][0],
                                        c[mt][nt][1] + scale * acc2[mt][nt][1]);
                float2 v1 = make_float2(c[mt][nt][2] + scale * acc2[mt][nt][2],
                                        c[mt][nt][3] + scale * acc2[mt][nt][3]);
                *(float2*)(out + base) = v0;
                *(float2*)(out + base + (size_t)8 * OO) = v1;
            }
    }
}

extern "C" void kernel_launch(void* const* d_in, const int* in_sizes, int n_in,
                              void* d_out, int out_size) {
    (void)in_sizes; (void)n_in; (void)out_size;
    const float* x        = (const float*)d_in[0];
    const float* W        = (const float*)d_in[1];
    const float* b        = (const float*)d_in[2];
    const float* A_sh     = (const float*)d_in[3];
    const float* B_sh     = (const float*)d_in[4];
    const float* A_tasks  = (const float*)d_in[5];
    const float* B_tasks  = (const float*)d_in[6];
    const float* tsc      = (const float*)d_in[7];
    float* out            = (float*)d_out;

    xa_kernel<<<BS_TOT / 128, 256>>>(x, A_sh, A_tasks);
    dim3 grid(OO / 128, BS_TOT / 128);
    main_kernel<<<grid, 256>>>(x, W, b, B_sh, B_tasks, tsc, out);
}